// round 9
// baseline (speedup 1.0000x reference)
#include <cuda_runtime.h>
#include <cuda_fp16.h>
#include <math.h>
#include <float.h>
#include <stdint.h>

#define S_LEN 2048
#define HID   2048
#define NHEAD 16
#define HS    128

// ---- scratch (no cudaMalloc allowed) ----
__device__ __half g_q[NHEAD * S_LEN * HS];
__device__ __half g_k[NHEAD * S_LEN * HS];
__device__ __half g_v[NHEAD * S_LEN * HS];
__device__ __half g_ctx[S_LEN * HID];
__device__ __half g_a[S_LEN * HID];            // hidden, fp16
__device__ __half g_wt_qkv[3 * HID * HID];     // W_qkv^T  [6144, 2048] fp16
__device__ __half g_wt_dense[HID * HID];       // W_dense^T [2048, 2048] fp16

// m16n8k16 fp16 mma, fp32 accumulate
__device__ __forceinline__ void mma_f16(float* d, const uint32_t* a,
                                        const uint32_t* b, const float* c) {
    asm volatile(
        "mma.sync.aligned.m16n8k16.row.col.f32.f16.f16.f32 "
        "{%0, %1, %2, %3}, {%4, %5, %6, %7}, {%8, %9}, {%10, %11, %12, %13};"
        : "=f"(d[0]), "=f"(d[1]), "=f"(d[2]), "=f"(d[3])
        : "r"(a[0]), "r"(a[1]), "r"(a[2]), "r"(a[3]),
          "r"(b[0]), "r"(b[1]),
          "f"(c[0]), "f"(c[1]), "f"(c[2]), "f"(c[3]));
}

__device__ __forceinline__ void ldsm_x4(uint32_t* r, uint32_t addr) {
    asm volatile("ldmatrix.sync.aligned.m8n8.x4.shared.b16 {%0, %1, %2, %3}, [%4];"
                 : "=r"(r[0]), "=r"(r[1]), "=r"(r[2]), "=r"(r[3]) : "r"(addr));
}
__device__ __forceinline__ void ldsm_x4t(uint32_t* r, uint32_t addr) {
    asm volatile("ldmatrix.sync.aligned.m8n8.x4.trans.shared.b16 {%0, %1, %2, %3}, [%4];"
                 : "=r"(r[0]), "=r"(r[1]), "=r"(r[2]), "=r"(r[3]) : "r"(addr));
}
__device__ __forceinline__ void cp_async16(uint32_t smem, const void* g) {
    asm volatile("cp.async.cg.shared.global [%0], [%1], 16;"
                 :: "r"(smem), "l"(g) : "memory");
}

// =====================================================================
// prep kernels
// =====================================================================
__global__ void __launch_bounds__(256) cvt_half_kernel(const float* __restrict__ in) {
    int i = blockIdx.x * blockDim.x + threadIdx.x;   // 8-float group
    float4 v0 = ((const float4*)in)[2 * i];
    float4 v1 = ((const float4*)in)[2 * i + 1];
    __half2 h[4];
    h[0] = __floats2half2_rn(v0.x, v0.y);
    h[1] = __floats2half2_rn(v0.z, v0.w);
    h[2] = __floats2half2_rn(v1.x, v1.y);
    h[3] = __floats2half2_rn(v1.z, v1.w);
    ((uint2*)g_a)[2 * i]     = make_uint2(*(uint32_t*)&h[0], *(uint32_t*)&h[1]);
    ((uint2*)g_a)[2 * i + 1] = make_uint2(*(uint32_t*)&h[2], *(uint32_t*)&h[3]);
}

// W [K, N] fp32 -> Wt [N, K] fp16
template<int WHICH>
__global__ void __launch_bounds__(256) transpose_half_kernel(const float* __restrict__ W,
                                                             int K, int N) {
    __shared__ float t[32][33];
    __half* Wt = (WHICH == 0) ? g_wt_qkv : g_wt_dense;
    int n0 = blockIdx.x * 32, k0 = blockIdx.y * 32;
    int tx = threadIdx.x & 31, ty = threadIdx.x >> 5;
#pragma unroll
    for (int i = 0; i < 32; i += 8)
        t[ty + i][tx] = W[(size_t)(k0 + ty + i) * N + n0 + tx];
    __syncthreads();
#pragma unroll
    for (int i = 0; i < 32; i += 8)
        Wt[(size_t)(n0 + ty + i) * K + k0 + tx] = __float2half(t[tx][ty + i]);
}

// =====================================================================
// fp16 tensor GEMM, 3-stage cp.async pipeline + ldmatrix fragments.
// block 128x128x32, 256 thr (8 warps 2x4), warp tile 64x32 (4x2 m16n8k16)
// __launch_bounds__(256,3): target 3 CTAs/SM (24 warps) for HMMA latency cover
// =====================================================================
#define ST2 40
#define STAGES 3
#define STG_HALFS (128 * ST2)
#define GEMM_SMEM (STAGES * 2 * STG_HALFS * (int)sizeof(__half))

template<int MODE>
__global__ void __launch_bounds__(256, 3)
tc_gemm(const float* __restrict__ bias, float* __restrict__ C, int K, int N)
{
    extern __shared__ __half smh[];
    __half* As = smh;                           // [STAGES][128*ST2]
    __half* Bs = smh + STAGES * STG_HALFS;

    const __half* A  = (MODE == 0) ? g_a : g_ctx;
    const __half* Bt = (MODE == 0) ? g_wt_qkv : g_wt_dense;

    int tid  = threadIdx.x;
    int lane = tid & 31, wid = tid >> 5;
    int bcol = blockIdx.x * 128;
    int brow = blockIdx.y * 128;
    int wm = (wid >> 2) * 64;
    int wn = (wid & 3) * 32;

    int g = lane >> 2;
    int t = lane & 3;
    int lm = lane & 7;              // row within 8x8 matrix
    int lq = (lane >> 3) & 1;
    int lh = lane >> 4;

    float acc[4][4][4];
#pragma unroll
    for (int mt = 0; mt < 4; mt++)
#pragma unroll
        for (int nt = 0; nt < 4; nt++)
#pragma unroll
            for (int r = 0; r < 4; r++) acc[mt][nt][r] = 0.f;

    // ldmatrix lane offsets (bytes), relative to stage base
    uint32_t a_lane_off = (uint32_t)((wm + lm + lq * 8) * ST2 + lh * 8) * 2u;
    uint32_t b_lane_off = (uint32_t)((wn + lm + lh * 8) * ST2 + lq * 8) * 2u;

    // staging: per matrix 128 rows x 32 halfs = 512 x 16B chunks
    int s_row = tid >> 2;            // 0..63 (+64)
    int s_c8  = (tid & 3) << 3;      // 0,8,16,24

    auto prefetch = [&](int kt, int s) {
        uint32_t a_base = (uint32_t)__cvta_generic_to_shared(&As[s * STG_HALFS]);
        uint32_t b_base = (uint32_t)__cvta_generic_to_shared(&Bs[s * STG_HALFS]);
#pragma unroll
        for (int it = 0; it < 2; it++) {
            int row = s_row + it * 64;
            uint32_t so = (uint32_t)(row * ST2 + s_c8) * 2u;
            cp_async16(a_base + so, A  + (size_t)(brow + row) * K + kt * 32 + s_c8);
            cp_async16(b_base + so, Bt + (size_t)(bcol + row) * K + kt * 32 + s_c8);
        }
        asm volatile("cp.async.commit_group;" ::: "memory");
    };

    const int NT = K / 32;
    prefetch(0, 0);
    prefetch(1, 1);

    for (int kt = 0; kt < NT; kt++) {
        asm volatile("cp.async.wait_group 1;" ::: "memory");
        __syncthreads();
        if (kt + 2 < NT) prefetch(kt + 2, (kt + 2) % STAGES);

        uint32_t a_s = (uint32_t)__cvta_generic_to_shared(
                           &As[(kt % STAGES) * STG_HALFS]) + a_lane_off;
        uint32_t b_s = (uint32_t)__cvta_generic_to_shared(
                           &Bs[(kt % STAGES) * STG_HALFS]) + b_lane_off;

#pragma unroll
        for (int kk = 0; kk < 2; kk++) {          // 2 x K=16
            uint32_t bf[4][2];
#pragma unroll
            for (int np = 0; np < 2; np++) {      // covers nt = 2np, 2np+1
                uint32_t br[4];
                ldsm_x4(br, b_s + (uint32_t)(np * 16 * ST2 + kk * 16) * 2u);
                bf[2 * np][0]     = br[0];
                bf[2 * np][1]     = br[1];
                bf[2 * np + 1][0] = br[2];
                bf[2 * np + 1][1] = br[3];
            }
#pragma unroll
            for (int mt = 0; mt < 4; mt++) {
                uint32_t af[4];
                ldsm_x4(af, a_s + (uint32_t)(mt * 16 * ST2 + kk * 16) * 2u);
#pragma unroll
                for (int nt = 0; nt < 4; nt++)
                    mma_f16(acc[mt][nt], af, bf[nt], acc[mt][nt]);
            }
        }
    }

    // ---- epilogue ----
    if (MODE == 0) {
        int kind = bcol >> 11;
        int head = (bcol & 2047) >> 7;
        __half* dstbase = (kind == 0 ? g_q : kind == 1 ? g_k : g_v)
                          + (size_t)head * S_LEN * HS;
#pragma unroll
        for (int mt = 0; mt < 4; mt++) {
#pragma unroll
            for (int nt = 0; nt < 4; nt++) {
                int col = wn + nt * 8 + 2 * t;    // within-head column
                int bi  = bcol + col;
                float bx = __ldg(&bias[bi]), by = __ldg(&bias[bi + 1]);
                int r0 = brow + wm + mt * 16 + g;
                __half2 v0 = __floats2half2_rn(acc[mt][nt][0] + bx, acc[mt][nt][1] + by);
                __half2 v1 = __floats2half2_rn(acc[mt][nt][2] + bx, acc[mt][nt][3] + by);
                *(__half2*)(dstbase + (size_t)r0 * HS + col)       = v0;
                *(__half2*)(dstbase + (size_t)(r0 + 8) * HS + col) = v1;
            }
        }
    } else {
#pragma unroll
        for (int mt = 0; mt < 4; mt++) {
#pragma unroll
            for (int nt = 0; nt < 4; nt++) {
                int col = bcol + wn + nt * 8 + 2 * t;
                float bx = __ldg(&bias[col]), by = __ldg(&bias[col + 1]);
                int r0 = brow + wm + mt * 16 + g;
                float2 v0 = make_float2(acc[mt][nt][0] + bx, acc[mt][nt][1] + by);
                float2 v1 = make_float2(acc[mt][nt][2] + bx, acc[mt][nt][3] + by);
                *(float2*)(C + (size_t)r0 * N + col)       = v0;
                *(float2*)(C + (size_t)(r0 + 8) * N + col) = v1;
            }
        }
    }
}

// =====================================================================
// fp16 tensorized flash attention + ldmatrix, causal, fp32 softmax.
// (unchanged from R8 passing version)
// =====================================================================
#define QS2 136
#define PS2 72

__global__ void __launch_bounds__(256) attn_kernel()
{
    extern __shared__ __half smha[];
    __half* Qs = smha;                        // 128*136
    __half* Ks = Qs + 128 * QS2;              // 64*136
    __half* Vs = Ks + 64 * QS2;               // 64*136
    __half* Ps = Vs + 64 * QS2;               // 128*72

    int tid  = threadIdx.x;
    int lane = tid & 31, wid = tid >> 5;
    int g = lane >> 2, t = lane & 3;
    int lm = lane & 7;
    int lq = (lane >> 3) & 1;
    int lh = lane >> 4;

    int qtile = (gridDim.x - 1) - blockIdx.x;   // heavy CTAs first
    int head  = blockIdx.y;
    const __half* Qp = g_q + (size_t)head * S_LEN * HS;
    const __half* Kp = g_k + (size_t)head * S_LEN * HS;
    const __half* Vp = g_v + (size_t)head * S_LEN * HS;

    int q0 = qtile * 128;

    // stage Q: 128x128 halfs = 2048 uint4
#pragma unroll
    for (int it = 0; it < 8; it++) {
        int idx = tid + it * 256;
        int r  = idx >> 4;
        int c8 = (idx & 15) << 3;
        *(uint4*)&Qs[r * QS2 + c8] = *(const uint4*)(Qp + (size_t)(q0 + r) * HS + c8);
    }

    const float scale = 0.08838834764831845f;   // 1/sqrt(128)
    int lr   = wid * 16 + g;
    int row0 = q0 + lr;

    uint32_t qs_base = (uint32_t)__cvta_generic_to_shared(Qs)
                     + (uint32_t)((wid * 16 + lm + lq * 8) * QS2 + lh * 8) * 2u;
    uint32_t ks_base = (uint32_t)__cvta_generic_to_shared(Ks)
                     + (uint32_t)((lm + lh * 8) * QS2 + lq * 8) * 2u;
    uint32_t vs_base = (uint32_t)__cvta_generic_to_shared(Vs)
                     + (uint32_t)((lm + lq * 8) * QS2 + lh * 8) * 2u;
    uint32_t ps_base = (uint32_t)__cvta_generic_to_shared(Ps)
                     + (uint32_t)((wid * 16 + lm + lq * 8) * PS2 + lh * 8) * 2u;

    float m0 = -FLT_MAX, m1 = -FLT_MAX, l0 = 0.f, l1 = 0.f;
    float o[16][4];
#pragma unroll
    for (int nt = 0; nt < 16; nt++)
#pragma unroll
        for (int r = 0; r < 4; r++) o[nt][r] = 0.f;

    int jmax = 2 * qtile + 1;
    for (int jt = 0; jt <= jmax; jt++) {
        int k0 = jt * 64;
        __syncthreads();                        // prior S/PV reads done

        // stage K and V (both row-major)
#pragma unroll
        for (int it = 0; it < 4; it++) {
            int idx = tid + it * 256;           // 0..1023
            int r  = idx >> 4;                  // token 0..63
            int c8 = (idx & 15) << 3;
            *(uint4*)&Ks[r * QS2 + c8] = *(const uint4*)(Kp + (size_t)(k0 + r) * HS + c8);
            *(uint4*)&Vs[r * QS2 + c8] = *(const uint4*)(Vp + (size_t)(k0 + r) * HS + c8);
        }
        __syncthreads();

        // ---- S = Q @ K^T : 16 rows x 64 cols per warp ----
        float sacc[8][4];
#pragma unroll
        for (int nt = 0; nt < 8; nt++)
#pragma unroll
            for (int r = 0; r < 4; r++) sacc[nt][r] = 0.f;

#pragma unroll
        for (int kk = 0; kk < 8; kk++) {        // 8 x K=16
            uint32_t af[4];
            ldsm_x4(af, qs_base + (uint32_t)(kk * 16) * 2u);
#pragma unroll
            for (int np = 0; np < 4; np++) {    // covers nt = 2np, 2np+1
                uint32_t br[4];
                ldsm_x4(br, ks_base + (uint32_t)(np * 16 * QS2 + kk * 16) * 2u);
                mma_f16(sacc[2 * np],     af, &br[0], sacc[2 * np]);
                mma_f16(sacc[2 * np + 1], af, &br[2], sacc[2 * np + 1]);
            }
        }

        // ---- scale + causal mask + online softmax ----
        bool diag = (jt >= 2 * qtile);
        float mx0 = -FLT_MAX, mx1 = -FLT_MAX;
#pragma unroll
        for (int nt = 0; nt < 8; nt++) {
            int colb = k0 + nt * 8 + 2 * t;
            float v0 = sacc[nt][0] * scale;
            float v1 = sacc[nt][1] * scale;
            float v2 = sacc[nt][2] * scale;
            float v3 = sacc[nt][3] * scale;
            if (diag) {
                if (colb     > row0)     v0 = -FLT_MAX;
                if (colb + 1 > row0)     v1 = -FLT_MAX;
                if (colb     > row0 + 8) v2 = -FLT_MAX;
                if (colb + 1 > row0 + 8) v3 = -FLT_MAX;
            }
            sacc[nt][0] = v0; sacc[nt][1] = v1;
            sacc[nt][2] = v2; sacc[nt][3] = v3;
            mx0 = fmaxf(mx0, fmaxf(v0, v1));
            mx1 = fmaxf(mx1, fmaxf(v2, v3));
        }
        mx0 = fmaxf(mx0, __shfl_xor_sync(0xffffffffu, mx0, 1));
        mx0 = fmaxf(mx0, __shfl_xor_sync(0xffffffffu, mx0, 2));
        mx1 = fmaxf(mx1, __shfl_xor_sync(0xffffffffu, mx1, 1));
        mx1 = fmaxf(mx1, __shfl_xor_sync(0xffffffffu, mx1, 2));
        float m0n = fmaxf(m0, mx0), m1n = fmaxf(m1, mx1);

        float s0 = 0.f, s1 = 0.f;
#pragma unroll
        for (int nt = 0; nt < 8; nt++) {
            float p0 = __expf(sacc[nt][0] - m0n);
            float p1 = __expf(sacc[nt][1] - m0n);
            float p2 = __expf(sacc[nt][2] - m1n);
            float p3 = __expf(sacc[nt][3] - m1n);
            s0 += p0 + p1;
            s1 += p2 + p3;
            *(__half2*)&Ps[lr * PS2 + nt * 8 + 2 * t]       = __floats2half2_rn(p0, p1);
            *(__half2*)&Ps[(lr + 8) * PS2 + nt * 8 + 2 * t] = __floats2half2_rn(p2, p3);
        }
        s0 += __shfl_xor_sync(0xffffffffu, s0, 1);
        s0 += __shfl_xor_sync(0xffffffffu, s0, 2);
        s1 += __shfl_xor_sync(0xffffffffu, s1, 1);
        s1 += __shfl_xor_sync(0xffffffffu, s1, 2);

        float sc0 = __expf(m0 - m0n), sc1 = __expf(m1 - m1n);
        l0 = l0 * sc0 + s0;  l1 = l1 * sc1 + s1;
        m0 = m0n;            m1 = m1n;
#pragma unroll
        for (int nt = 0; nt < 16; nt++) {
            o[nt][0] *= sc0; o[nt][1] *= sc0;
            o[nt][2] *= sc1; o[nt][3] *= sc1;
        }
        __syncwarp();    // Ps rows of this warp visible warp-wide

        // ---- O += P @ V ----
#pragma unroll
        for (int kk = 0; kk < 4; kk++) {        // 4 x K=16 over 64 tokens
            uint32_t af[4];
            ldsm_x4(af, ps_base + (uint32_t)(kk * 16) * 2u);
#pragma unroll
            for (int np = 0; np < 8; np++) {    // covers nt = 2np, 2np+1
                uint32_t br[4];
                ldsm_x4t(br, vs_base + (uint32_t)(kk * 16 * QS2 + np * 16) * 2u);
                mma_f16(o[2 * np],     af, &br[0], o[2 * np]);
                mma_f16(o[2 * np + 1], af, &br[2], o[2 * np + 1]);
            }
        }
    }

    // ---- epilogue: normalize, store to g_ctx (fp16) ----
    float inv0 = 1.f / l0, inv1 = 1.f / l1;
    __half* dst0 = g_ctx + (size_t)row0 * HID + head * HS;
    __half* dst1 = dst0 + (size_t)8 * HID;
#pragma unroll
    for (int nt = 0; nt < 16; nt++) {
        int c = nt * 8 + 2 * t;
        *(__half2*)(dst0 + c) = __floats2half2_rn(o[nt][0] * inv0, o[nt][1] * inv0);
        *(__half2*)(dst1 + c) = __floats2half2_rn(o[nt][2] * inv1, o[nt][3] * inv1);
    }
}

// =====================================================================
// launch
// =====================================================================
extern "C" void kernel_launch(void* const* d_in, const int* in_sizes, int n_in,
                              void* d_out, int out_size)
{
    const float* hidden  = (const float*)d_in[0];
    // d_in[1] = ltor_mask (always causal tril; handled analytically)
    const float* W_qkv   = (const float*)d_in[2];
    const float* b_qkv   = (const float*)d_in[3];
    const float* W_dense = (const float*)d_in[4];
    const float* b_dense = (const float*)d_in[5];
    float* out = (float*)d_out;

    const int ATTN_SMEM = (128 * QS2 + 64 * QS2 + 64 * QS2 + 128 * PS2)
                          * (int)sizeof(__half);   // 88064 B
    cudaFuncSetAttribute(attn_kernel,
                         cudaFuncAttributeMaxDynamicSharedMemorySize, ATTN_SMEM);
    cudaFuncSetAttribute(tc_gemm<0>,
                         cudaFuncAttributeMaxDynamicSharedMemorySize, GEMM_SMEM);
    cudaFuncSetAttribute(tc_gemm<1>,
                         cudaFuncAttributeMaxDynamicSharedMemorySize, GEMM_SMEM);

    // prep: fp16 conversions
    cvt_half_kernel<<<(S_LEN * HID / 8) / 256, 256>>>(hidden);
    transpose_half_kernel<0><<<dim3(3 * HID / 32, HID / 32), 256>>>(W_qkv, HID, 3 * HID);
    transpose_half_kernel<1><<<dim3(HID / 32, HID / 32), 256>>>(W_dense, HID, HID);

    // 1) QKV projection (fp16 tensor + ldmatrix, 3 CTA/SM), scatter head-major
    tc_gemm<0><<<dim3(3 * HID / 128, S_LEN / 128), 256, GEMM_SMEM>>>(b_qkv, nullptr,
                                                                     HID, 3 * HID);
    // 2) causal flash attention (fp16 tensor + ldmatrix) -> g_ctx
    attn_kernel<<<dim3(16, 16), 256, ATTN_SMEM>>>();

    // 3) dense projection (fp16 tensor + ldmatrix, 3 CTA/SM)
    tc_gemm<1><<<dim3(HID / 128, S_LEN / 128), 256, GEMM_SMEM>>>(b_dense, out,
                                                                 HID, HID);
}

// round 10
// speedup vs baseline: 1.4339x; 1.4339x over previous
#include <cuda_runtime.h>
#include <cuda_fp16.h>
#include <math.h>
#include <float.h>
#include <stdint.h>

#define S_LEN 2048
#define HID   2048
#define NHEAD 16
#define HS    128

// ---- scratch (no cudaMalloc allowed) ----
__device__ __half g_q[NHEAD * S_LEN * HS];
__device__ __half g_k[NHEAD * S_LEN * HS];
__device__ __half g_v[NHEAD * S_LEN * HS];
__device__ __half g_ctx[S_LEN * HID];
__device__ __half g_a[S_LEN * HID];            // hidden, fp16 [2048, 2048]
__device__ __half g_w_qkv[HID * 3 * HID];      // W_qkv fp16 [2048, 6144] (NOT transposed)
__device__ __half g_w_dense[HID * HID];        // W_dense fp16 [2048, 2048]

// m16n8k16 fp16 mma, fp32 accumulate
__device__ __forceinline__ void mma_f16(float* d, const uint32_t* a,
                                        const uint32_t* b, const float* c) {
    asm volatile(
        "mma.sync.aligned.m16n8k16.row.col.f32.f16.f16.f32 "
        "{%0, %1, %2, %3}, {%4, %5, %6, %7}, {%8, %9}, {%10, %11, %12, %13};"
        : "=f"(d[0]), "=f"(d[1]), "=f"(d[2]), "=f"(d[3])
        : "r"(a[0]), "r"(a[1]), "r"(a[2]), "r"(a[3]),
          "r"(b[0]), "r"(b[1]),
          "f"(c[0]), "f"(c[1]), "f"(c[2]), "f"(c[3]));
}

__device__ __forceinline__ void ldsm_x4(uint32_t* r, uint32_t addr) {
    asm volatile("ldmatrix.sync.aligned.m8n8.x4.shared.b16 {%0, %1, %2, %3}, [%4];"
                 : "=r"(r[0]), "=r"(r[1]), "=r"(r[2]), "=r"(r[3]) : "r"(addr));
}
__device__ __forceinline__ void ldsm_x4t(uint32_t* r, uint32_t addr) {
    asm volatile("ldmatrix.sync.aligned.m8n8.x4.trans.shared.b16 {%0, %1, %2, %3}, [%4];"
                 : "=r"(r[0]), "=r"(r[1]), "=r"(r[2]), "=r"(r[3]) : "r"(addr));
}
__device__ __forceinline__ void cp_async16(uint32_t smem, const void* g) {
    asm volatile("cp.async.cg.shared.global [%0], [%1], 16;"
                 :: "r"(smem), "l"(g) : "memory");
}

// =====================================================================
// prep: ONE flat fp32 -> fp16 convert over hidden + W_qkv + W_dense
// (no transposes — GEMM reads W row-major via ldmatrix.trans)
// =====================================================================
#define N_H8  (S_LEN * HID / 8)            // 524288
#define N_WQ8 (HID * 3 * HID / 8)          // 1572864
#define N_WD8 (HID * HID / 8)              // 524288

__global__ void __launch_bounds__(256) cvt_all_kernel(const float* __restrict__ h,
                                                      const float* __restrict__ wq,
                                                      const float* __restrict__ wd) {
    size_t i = (size_t)blockIdx.x * 256 + threadIdx.x;   // 8-float group
    const float* src;
    __half* dst;
    size_t off;
    if (i < N_H8)             { src = h;  dst = g_a;       off = i; }
    else if (i < N_H8 + N_WQ8){ src = wq; dst = g_w_qkv;   off = i - N_H8; }
    else                      { src = wd; dst = g_w_dense; off = i - N_H8 - N_WQ8; }
    float4 v0 = ((const float4*)src)[2 * off];
    float4 v1 = ((const float4*)src)[2 * off + 1];
    __half2 h0 = __floats2half2_rn(v0.x, v0.y);
    __half2 h1 = __floats2half2_rn(v0.z, v0.w);
    __half2 h2 = __floats2half2_rn(v1.x, v1.y);
    __half2 h3 = __floats2half2_rn(v1.z, v1.w);
    uint4 packed = make_uint4(*(uint32_t*)&h0, *(uint32_t*)&h1,
                              *(uint32_t*)&h2, *(uint32_t*)&h3);
    *(uint4*)(dst + 8 * off) = packed;
}

// =====================================================================
// fp16 tensor GEMM: D[M,N] = A[M,K] @ W[K,N] + bias
// 4-stage cp.async pipeline, ldmatrix fragments (B via ldmatrix.trans).
// block 128x128x32, 256 thr (8 warps 2x4), warp tile 64x32 (4x2 m16n8k16)
// A stage: 128 rows x 32 halfs, stride 40 (conflict-free ldsm)
// B stage: 32 k-rows x 128 n-halfs, stride 136 (conflict-free ldsm.trans)
// =====================================================================
#define ST2 40
#define BST 136
#define STAGES 4
#define A_STG (128 * ST2)                  // 5120 halfs
#define B_STG (32 * BST)                   // 4352 halfs
#define STG_HALFS (A_STG + B_STG)          // 9472
#define GEMM_SMEM (STAGES * STG_HALFS * (int)sizeof(__half))   // 75776 B

template<int MODE>
__global__ void __launch_bounds__(256)
tc_gemm(const float* __restrict__ bias, float* __restrict__ C, int K, int N)
{
    extern __shared__ __half smh[];

    const __half* A = (MODE == 0) ? g_a : g_ctx;
    const __half* B = (MODE == 0) ? g_w_qkv : g_w_dense;

    int tid  = threadIdx.x;
    int lane = tid & 31, wid = tid >> 5;
    int bcol = blockIdx.x * 128;
    int brow = blockIdx.y * 128;
    int wm = (wid >> 2) * 64;
    int wn = (wid & 3) * 32;

    int g = lane >> 2;
    int t = lane & 3;
    int lm = lane & 7;
    int lq = (lane >> 3) & 1;
    int lh = lane >> 4;

    float acc[4][4][4];
#pragma unroll
    for (int mt = 0; mt < 4; mt++)
#pragma unroll
        for (int nt = 0; nt < 4; nt++)
#pragma unroll
            for (int r = 0; r < 4; r++) acc[mt][nt][r] = 0.f;

    // ldmatrix lane offsets (halfs)
    uint32_t a_lane = (uint32_t)((wm + lm + lq * 8) * ST2 + lh * 8);
    uint32_t b_lane = (uint32_t)((lm + lq * 8) * BST + wn + lh * 8);

    // staging coords
    int sa_row = tid >> 2;            // A: 0..63 (+64)
    int sa_c8  = (tid & 3) << 3;      // 0,8,16,24 halfs
    int sb_row = tid >> 3;            // B: 0..31
    int sb_c8  = (tid & 7) << 3;      // halfs 0..56 (second chunk +64)

    auto prefetch = [&](int kt, int s) {
        uint32_t base = (uint32_t)__cvta_generic_to_shared(smh + s * STG_HALFS);
#pragma unroll
        for (int it = 0; it < 2; it++) {
            int row = sa_row + it * 64;
            cp_async16(base + (uint32_t)(row * ST2 + sa_c8) * 2u,
                       A + (size_t)(brow + row) * K + kt * 32 + sa_c8);
        }
        const __half* bsrc = B + (size_t)(kt * 32 + sb_row) * N + bcol + sb_c8;
        uint32_t bdst = base + (uint32_t)(A_STG + sb_row * BST + sb_c8) * 2u;
        cp_async16(bdst,            bsrc);
        cp_async16(bdst + 64u * 2u, bsrc + 64);
        asm volatile("cp.async.commit_group;" ::: "memory");
    };

    const int NT = K / 32;
    prefetch(0, 0);
    prefetch(1, 1);
    prefetch(2, 2);

    for (int kt = 0; kt < NT; kt++) {
        asm volatile("cp.async.wait_group 2;" ::: "memory");
        __syncthreads();
        if (kt + 3 < NT) prefetch(kt + 3, (kt + 3) & 3);
        else asm volatile("cp.async.commit_group;" ::: "memory");  // keep invariant

        uint32_t stage = (uint32_t)__cvta_generic_to_shared(
                             smh + (kt & 3) * STG_HALFS);
        uint32_t a_s = stage + a_lane * 2u;
        uint32_t b_s = stage + (uint32_t)A_STG * 2u + b_lane * 2u;

#pragma unroll
        for (int kk = 0; kk < 2; kk++) {          // 2 x K=16
            uint32_t bf[4][2];
#pragma unroll
            for (int np = 0; np < 2; np++) {      // n-subtiles of 16 -> nt pairs
                uint32_t br[4];
                ldsm_x4t(br, b_s + (uint32_t)(kk * 16 * BST + np * 16) * 2u);
                bf[2 * np][0]     = br[0];
                bf[2 * np][1]     = br[1];
                bf[2 * np + 1][0] = br[2];
                bf[2 * np + 1][1] = br[3];
            }
#pragma unroll
            for (int mt = 0; mt < 4; mt++) {
                uint32_t af[4];
                ldsm_x4(af, a_s + (uint32_t)(mt * 16 * ST2 + kk * 16) * 2u);
#pragma unroll
                for (int nt = 0; nt < 4; nt++)
                    mma_f16(acc[mt][nt], af, bf[nt], acc[mt][nt]);
            }
        }
    }

    // ---- epilogue ----
    if (MODE == 0) {
        int kind = bcol >> 11;
        int head = (bcol & 2047) >> 7;
        __half* dstbase = (kind == 0 ? g_q : kind == 1 ? g_k : g_v)
                          + (size_t)head * S_LEN * HS;
#pragma unroll
        for (int mt = 0; mt < 4; mt++) {
#pragma unroll
            for (int nt = 0; nt < 4; nt++) {
                int col = wn + nt * 8 + 2 * t;    // within-head column
                int bi  = bcol + col;
                float bx = __ldg(&bias[bi]), by = __ldg(&bias[bi + 1]);
                int r0 = brow + wm + mt * 16 + g;
                __half2 v0 = __floats2half2_rn(acc[mt][nt][0] + bx, acc[mt][nt][1] + by);
                __half2 v1 = __floats2half2_rn(acc[mt][nt][2] + bx, acc[mt][nt][3] + by);
                *(__half2*)(dstbase + (size_t)r0 * HS + col)       = v0;
                *(__half2*)(dstbase + (size_t)(r0 + 8) * HS + col) = v1;
            }
        }
    } else {
#pragma unroll
        for (int mt = 0; mt < 4; mt++) {
#pragma unroll
            for (int nt = 0; nt < 4; nt++) {
                int col = bcol + wn + nt * 8 + 2 * t;
                float bx = __ldg(&bias[col]), by = __ldg(&bias[col + 1]);
                int r0 = brow + wm + mt * 16 + g;
                float2 v0 = make_float2(acc[mt][nt][0] + bx, acc[mt][nt][1] + by);
                float2 v1 = make_float2(acc[mt][nt][2] + bx, acc[mt][nt][3] + by);
                *(float2*)(C + (size_t)r0 * N + col)       = v0;
                *(float2*)(C + (size_t)(r0 + 8) * N + col) = v1;
            }
        }
    }
}

// =====================================================================
// fp16 tensorized flash attention + ldmatrix, causal, fp32 softmax.
// (verbatim from R8 passing version)
// =====================================================================
#define QS2 136
#define PS2 72

__global__ void __launch_bounds__(256) attn_kernel()
{
    extern __shared__ __half smha[];
    __half* Qs = smha;                        // 128*136
    __half* Ks = Qs + 128 * QS2;              // 64*136
    __half* Vs = Ks + 64 * QS2;               // 64*136
    __half* Ps = Vs + 64 * QS2;               // 128*72

    int tid  = threadIdx.x;
    int lane = tid & 31, wid = tid >> 5;
    int g = lane >> 2, t = lane & 3;
    int lm = lane & 7;
    int lq = (lane >> 3) & 1;
    int lh = lane >> 4;

    int qtile = (gridDim.x - 1) - blockIdx.x;   // heavy CTAs first
    int head  = blockIdx.y;
    const __half* Qp = g_q + (size_t)head * S_LEN * HS;
    const __half* Kp = g_k + (size_t)head * S_LEN * HS;
    const __half* Vp = g_v + (size_t)head * S_LEN * HS;

    int q0 = qtile * 128;

#pragma unroll
    for (int it = 0; it < 8; it++) {
        int idx = tid + it * 256;
        int r  = idx >> 4;
        int c8 = (idx & 15) << 3;
        *(uint4*)&Qs[r * QS2 + c8] = *(const uint4*)(Qp + (size_t)(q0 + r) * HS + c8);
    }

    const float scale = 0.08838834764831845f;   // 1/sqrt(128)
    int lr   = wid * 16 + g;
    int row0 = q0 + lr;

    uint32_t qs_base = (uint32_t)__cvta_generic_to_shared(Qs)
                     + (uint32_t)((wid * 16 + lm + lq * 8) * QS2 + lh * 8) * 2u;
    uint32_t ks_base = (uint32_t)__cvta_generic_to_shared(Ks)
                     + (uint32_t)((lm + lh * 8) * QS2 + lq * 8) * 2u;
    uint32_t vs_base = (uint32_t)__cvta_generic_to_shared(Vs)
                     + (uint32_t)((lm + lq * 8) * QS2 + lh * 8) * 2u;
    uint32_t ps_base = (uint32_t)__cvta_generic_to_shared(Ps)
                     + (uint32_t)((wid * 16 + lm + lq * 8) * PS2 + lh * 8) * 2u;

    float m0 = -FLT_MAX, m1 = -FLT_MAX, l0 = 0.f, l1 = 0.f;
    float o[16][4];
#pragma unroll
    for (int nt = 0; nt < 16; nt++)
#pragma unroll
        for (int r = 0; r < 4; r++) o[nt][r] = 0.f;

    int jmax = 2 * qtile + 1;
    for (int jt = 0; jt <= jmax; jt++) {
        int k0 = jt * 64;
        __syncthreads();

#pragma unroll
        for (int it = 0; it < 4; it++) {
            int idx = tid + it * 256;
            int r  = idx >> 4;
            int c8 = (idx & 15) << 3;
            *(uint4*)&Ks[r * QS2 + c8] = *(const uint4*)(Kp + (size_t)(k0 + r) * HS + c8);
            *(uint4*)&Vs[r * QS2 + c8] = *(const uint4*)(Vp + (size_t)(k0 + r) * HS + c8);
        }
        __syncthreads();

        float sacc[8][4];
#pragma unroll
        for (int nt = 0; nt < 8; nt++)
#pragma unroll
            for (int r = 0; r < 4; r++) sacc[nt][r] = 0.f;

#pragma unroll
        for (int kk = 0; kk < 8; kk++) {
            uint32_t af[4];
            ldsm_x4(af, qs_base + (uint32_t)(kk * 16) * 2u);
#pragma unroll
            for (int np = 0; np < 4; np++) {
                uint32_t br[4];
                ldsm_x4(br, ks_base + (uint32_t)(np * 16 * QS2 + kk * 16) * 2u);
                mma_f16(sacc[2 * np],     af, &br[0], sacc[2 * np]);
                mma_f16(sacc[2 * np + 1], af, &br[2], sacc[2 * np + 1]);
            }
        }

        bool diag = (jt >= 2 * qtile);
        float mx0 = -FLT_MAX, mx1 = -FLT_MAX;
#pragma unroll
        for (int nt = 0; nt < 8; nt++) {
            int colb = k0 + nt * 8 + 2 * t;
            float v0 = sacc[nt][0] * scale;
            float v1 = sacc[nt][1] * scale;
            float v2 = sacc[nt][2] * scale;
            float v3 = sacc[nt][3] * scale;
            if (diag) {
                if (colb     > row0)     v0 = -FLT_MAX;
                if (colb + 1 > row0)     v1 = -FLT_MAX;
                if (colb     > row0 + 8) v2 = -FLT_MAX;
                if (colb + 1 > row0 + 8) v3 = -FLT_MAX;
            }
            sacc[nt][0] = v0; sacc[nt][1] = v1;
            sacc[nt][2] = v2; sacc[nt][3] = v3;
            mx0 = fmaxf(mx0, fmaxf(v0, v1));
            mx1 = fmaxf(mx1, fmaxf(v2, v3));
        }
        mx0 = fmaxf(mx0, __shfl_xor_sync(0xffffffffu, mx0, 1));
        mx0 = fmaxf(mx0, __shfl_xor_sync(0xffffffffu, mx0, 2));
        mx1 = fmaxf(mx1, __shfl_xor_sync(0xffffffffu, mx1, 1));
        mx1 = fmaxf(mx1, __shfl_xor_sync(0xffffffffu, mx1, 2));
        float m0n = fmaxf(m0, mx0), m1n = fmaxf(m1, mx1);

        float s0 = 0.f, s1 = 0.f;
#pragma unroll
        for (int nt = 0; nt < 8; nt++) {
            float p0 = __expf(sacc[nt][0] - m0n);
            float p1 = __expf(sacc[nt][1] - m0n);
            float p2 = __expf(sacc[nt][2] - m1n);
            float p3 = __expf(sacc[nt][3] - m1n);
            s0 += p0 + p1;
            s1 += p2 + p3;
            *(__half2*)&Ps[lr * PS2 + nt * 8 + 2 * t]       = __floats2half2_rn(p0, p1);
            *(__half2*)&Ps[(lr + 8) * PS2 + nt * 8 + 2 * t] = __floats2half2_rn(p2, p3);
        }
        s0 += __shfl_xor_sync(0xffffffffu, s0, 1);
        s0 += __shfl_xor_sync(0xffffffffu, s0, 2);
        s1 += __shfl_xor_sync(0xffffffffu, s1, 1);
        s1 += __shfl_xor_sync(0xffffffffu, s1, 2);

        float sc0 = __expf(m0 - m0n), sc1 = __expf(m1 - m1n);
        l0 = l0 * sc0 + s0;  l1 = l1 * sc1 + s1;
        m0 = m0n;            m1 = m1n;
#pragma unroll
        for (int nt = 0; nt < 16; nt++) {
            o[nt][0] *= sc0; o[nt][1] *= sc0;
            o[nt][2] *= sc1; o[nt][3] *= sc1;
        }
        __syncwarp();

#pragma unroll
        for (int kk = 0; kk < 4; kk++) {
            uint32_t af[4];
            ldsm_x4(af, ps_base + (uint32_t)(kk * 16) * 2u);
#pragma unroll
            for (int np = 0; np < 8; np++) {
                uint32_t br[4];
                ldsm_x4t(br, vs_base + (uint32_t)(kk * 16 * QS2 + np * 16) * 2u);
                mma_f16(o[2 * np],     af, &br[0], o[2 * np]);
                mma_f16(o[2 * np + 1], af, &br[2], o[2 * np + 1]);
            }
        }
    }

    float inv0 = 1.f / l0, inv1 = 1.f / l1;
    __half* dst0 = g_ctx + (size_t)row0 * HID + head * HS;
    __half* dst1 = dst0 + (size_t)8 * HID;
#pragma unroll
    for (int nt = 0; nt < 16; nt++) {
        int c = nt * 8 + 2 * t;
        *(__half2*)(dst0 + c) = __floats2half2_rn(o[nt][0] * inv0, o[nt][1] * inv0);
        *(__half2*)(dst1 + c) = __floats2half2_rn(o[nt][2] * inv1, o[nt][3] * inv1);
    }
}

// =====================================================================
// launch
// =====================================================================
extern "C" void kernel_launch(void* const* d_in, const int* in_sizes, int n_in,
                              void* d_out, int out_size)
{
    const float* hidden  = (const float*)d_in[0];
    // d_in[1] = ltor_mask (always causal tril; handled analytically)
    const float* W_qkv   = (const float*)d_in[2];
    const float* b_qkv   = (const float*)d_in[3];
    const float* W_dense = (const float*)d_in[4];
    const float* b_dense = (const float*)d_in[5];
    float* out = (float*)d_out;

    const int ATTN_SMEM = (128 * QS2 + 64 * QS2 + 64 * QS2 + 128 * PS2)
                          * (int)sizeof(__half);   // 88064 B
    cudaFuncSetAttribute(attn_kernel,
                         cudaFuncAttributeMaxDynamicSharedMemorySize, ATTN_SMEM);
    cudaFuncSetAttribute(tc_gemm<0>,
                         cudaFuncAttributeMaxDynamicSharedMemorySize, GEMM_SMEM);
    cudaFuncSetAttribute(tc_gemm<1>,
                         cudaFuncAttributeMaxDynamicSharedMemorySize, GEMM_SMEM);

    // prep: single fused fp32 -> fp16 convert (no transposes)
    cvt_all_kernel<<<(N_H8 + N_WQ8 + N_WD8) / 256, 256>>>(hidden, W_qkv, W_dense);

    // 1) QKV projection (fp16 tensor + ldmatrix.trans B), scatter head-major
    tc_gemm<0><<<dim3(3 * HID / 128, S_LEN / 128), 256, GEMM_SMEM>>>(b_qkv, nullptr,
                                                                     HID, 3 * HID);
    // 2) causal flash attention (fp16 tensor + ldmatrix) -> g_ctx
    attn_kernel<<<dim3(16, 16), 256, ATTN_SMEM>>>();

    // 3) dense projection
    tc_gemm<1><<<dim3(HID / 128, S_LEN / 128), 256, GEMM_SMEM>>>(b_dense, out,
                                                                 HID, HID);
}

// round 11
// speedup vs baseline: 1.4717x; 1.0264x over previous
#include <cuda_runtime.h>
#include <cuda_fp16.h>
#include <math.h>
#include <float.h>
#include <stdint.h>

#define S_LEN 2048
#define HID   2048
#define NHEAD 16
#define HS    128

// ---- scratch (no cudaMalloc allowed) ----
__device__ __half g_q[NHEAD * S_LEN * HS];
__device__ __half g_k[NHEAD * S_LEN * HS];
__device__ __half g_v[NHEAD * S_LEN * HS];
__device__ __half g_ctx[S_LEN * HID];
__device__ __half g_a[S_LEN * HID];            // hidden, fp16 [2048, 2048]
__device__ __half g_w_qkv[HID * 3 * HID];      // W_qkv fp16 [2048, 6144]
__device__ __half g_w_dense[HID * HID];        // W_dense fp16 [2048, 2048]

// m16n8k16 fp16 mma, fp32 accumulate
__device__ __forceinline__ void mma_f16(float* d, const uint32_t* a,
                                        const uint32_t* b, const float* c) {
    asm volatile(
        "mma.sync.aligned.m16n8k16.row.col.f32.f16.f16.f32 "
        "{%0, %1, %2, %3}, {%4, %5, %6, %7}, {%8, %9}, {%10, %11, %12, %13};"
        : "=f"(d[0]), "=f"(d[1]), "=f"(d[2]), "=f"(d[3])
        : "r"(a[0]), "r"(a[1]), "r"(a[2]), "r"(a[3]),
          "r"(b[0]), "r"(b[1]),
          "f"(c[0]), "f"(c[1]), "f"(c[2]), "f"(c[3]));
}

__device__ __forceinline__ void ldsm_x4(uint32_t* r, uint32_t addr) {
    asm volatile("ldmatrix.sync.aligned.m8n8.x4.shared.b16 {%0, %1, %2, %3}, [%4];"
                 : "=r"(r[0]), "=r"(r[1]), "=r"(r[2]), "=r"(r[3]) : "r"(addr));
}
__device__ __forceinline__ void ldsm_x4t(uint32_t* r, uint32_t addr) {
    asm volatile("ldmatrix.sync.aligned.m8n8.x4.trans.shared.b16 {%0, %1, %2, %3}, [%4];"
                 : "=r"(r[0]), "=r"(r[1]), "=r"(r[2]), "=r"(r[3]) : "r"(addr));
}
__device__ __forceinline__ void cp_async16(uint32_t smem, const void* g) {
    asm volatile("cp.async.cg.shared.global [%0], [%1], 16;"
                 :: "r"(smem), "l"(g) : "memory");
}

// =====================================================================
// prep: ONE flat fp32 -> fp16 convert over hidden + W_qkv + W_dense
// =====================================================================
#define N_H8  (S_LEN * HID / 8)
#define N_WQ8 (HID * 3 * HID / 8)
#define N_WD8 (HID * HID / 8)

__global__ void __launch_bounds__(256) cvt_all_kernel(const float* __restrict__ h,
                                                      const float* __restrict__ wq,
                                                      const float* __restrict__ wd) {
    size_t i = (size_t)blockIdx.x * 256 + threadIdx.x;
    const float* src;
    __half* dst;
    size_t off;
    if (i < N_H8)             { src = h;  dst = g_a;       off = i; }
    else if (i < N_H8 + N_WQ8){ src = wq; dst = g_w_qkv;   off = i - N_H8; }
    else                      { src = wd; dst = g_w_dense; off = i - N_H8 - N_WQ8; }
    float4 v0 = ((const float4*)src)[2 * off];
    float4 v1 = ((const float4*)src)[2 * off + 1];
    __half2 h0 = __floats2half2_rn(v0.x, v0.y);
    __half2 h1 = __floats2half2_rn(v0.z, v0.w);
    __half2 h2 = __floats2half2_rn(v1.x, v1.y);
    __half2 h3 = __floats2half2_rn(v1.z, v1.w);
    uint4 packed = make_uint4(*(uint32_t*)&h0, *(uint32_t*)&h1,
                              *(uint32_t*)&h2, *(uint32_t*)&h3);
    *(uint4*)(dst + 8 * off) = packed;
}

// =====================================================================
// fp16 tensor GEMM: D[M,N] = A[M,K] @ W[K,N] + bias
// 4-stage cp.async pipeline + software-pipelined ldmatrix fragments.
// =====================================================================
#define ST2 40
#define BST 136
#define STAGES 4
#define A_STG (128 * ST2)
#define B_STG (32 * BST)
#define STG_HALFS (A_STG + B_STG)
#define GEMM_SMEM (STAGES * STG_HALFS * (int)sizeof(__half))

template<int MODE>
__global__ void __launch_bounds__(256)
tc_gemm(const float* __restrict__ bias, float* __restrict__ C, int K, int N)
{
    extern __shared__ __half smh[];

    const __half* A = (MODE == 0) ? g_a : g_ctx;
    const __half* B = (MODE == 0) ? g_w_qkv : g_w_dense;

    int tid  = threadIdx.x;
    int lane = tid & 31, wid = tid >> 5;
    int bcol = blockIdx.x * 128;
    int brow = blockIdx.y * 128;
    int wm = (wid >> 2) * 64;
    int wn = (wid & 3) * 32;

    int g = lane >> 2;
    int t = lane & 3;
    int lm = lane & 7;
    int lq = (lane >> 3) & 1;
    int lh = lane >> 4;

    float acc[4][4][4];
#pragma unroll
    for (int mt = 0; mt < 4; mt++)
#pragma unroll
        for (int nt = 0; nt < 4; nt++)
#pragma unroll
            for (int r = 0; r < 4; r++) acc[mt][nt][r] = 0.f;

    uint32_t a_lane = (uint32_t)((wm + lm + lq * 8) * ST2 + lh * 8);
    uint32_t b_lane = (uint32_t)((lm + lq * 8) * BST + wn + lh * 8);

    int sa_row = tid >> 2;
    int sa_c8  = (tid & 3) << 3;
    int sb_row = tid >> 3;
    int sb_c8  = (tid & 7) << 3;

    auto prefetch = [&](int kt, int s) {
        uint32_t base = (uint32_t)__cvta_generic_to_shared(smh + s * STG_HALFS);
#pragma unroll
        for (int it = 0; it < 2; it++) {
            int row = sa_row + it * 64;
            cp_async16(base + (uint32_t)(row * ST2 + sa_c8) * 2u,
                       A + (size_t)(brow + row) * K + kt * 32 + sa_c8);
        }
        const __half* bsrc = B + (size_t)(kt * 32 + sb_row) * N + bcol + sb_c8;
        uint32_t bdst = base + (uint32_t)(A_STG + sb_row * BST + sb_c8) * 2u;
        cp_async16(bdst,            bsrc);
        cp_async16(bdst + 64u * 2u, bsrc + 64);
        asm volatile("cp.async.commit_group;" ::: "memory");
    };

    const int NT = K / 32;
    prefetch(0, 0);
    prefetch(1, 1);
    prefetch(2, 2);

    for (int kt = 0; kt < NT; kt++) {
        asm volatile("cp.async.wait_group 2;" ::: "memory");
        __syncthreads();
        if (kt + 3 < NT) prefetch(kt + 3, (kt + 3) & 3);
        else asm volatile("cp.async.commit_group;" ::: "memory");

        uint32_t stage = (uint32_t)__cvta_generic_to_shared(
                             smh + (kt & 3) * STG_HALFS);
        uint32_t a_s = stage + a_lane * 2u;
        uint32_t b_s = stage + (uint32_t)A_STG * 2u + b_lane * 2u;

        // preload all B fragments for both K=16 halves (4 LDSM)
        uint32_t bf[2][4][2];
#pragma unroll
        for (int kk = 0; kk < 2; kk++)
#pragma unroll
            for (int np = 0; np < 2; np++) {
                uint32_t br[4];
                ldsm_x4t(br, b_s + (uint32_t)(kk * 16 * BST + np * 16) * 2u);
                bf[kk][2 * np][0]     = br[0];
                bf[kk][2 * np][1]     = br[1];
                bf[kk][2 * np + 1][0] = br[2];
                bf[kk][2 * np + 1][1] = br[3];
            }

        // software-pipelined A fragments over 8 (kk,mt) groups
        uint32_t af[2][4];
        ldsm_x4(af[0], a_s);                      // (kk=0, mt=0)
#pragma unroll
        for (int s = 0; s < 8; s++) {
            int kk = s >> 2, mt = s & 3;
            if (s < 7) {
                int s1 = s + 1;
                int kk1 = s1 >> 2, mt1 = s1 & 3;
                ldsm_x4(af[s1 & 1],
                        a_s + (uint32_t)(mt1 * 16 * ST2 + kk1 * 16) * 2u);
            }
#pragma unroll
            for (int nt = 0; nt < 4; nt++)
                mma_f16(acc[mt][nt], af[s & 1], bf[kk][nt], acc[mt][nt]);
        }
    }

    // ---- epilogue ----
    if (MODE == 0) {
        int kind = bcol >> 11;
        int head = (bcol & 2047) >> 7;
        __half* dstbase = (kind == 0 ? g_q : kind == 1 ? g_k : g_v)
                          + (size_t)head * S_LEN * HS;
#pragma unroll
        for (int mt = 0; mt < 4; mt++) {
#pragma unroll
            for (int nt = 0; nt < 4; nt++) {
                int col = wn + nt * 8 + 2 * t;
                int bi  = bcol + col;
                float bx = __ldg(&bias[bi]), by = __ldg(&bias[bi + 1]);
                int r0 = brow + wm + mt * 16 + g;
                __half2 v0 = __floats2half2_rn(acc[mt][nt][0] + bx, acc[mt][nt][1] + by);
                __half2 v1 = __floats2half2_rn(acc[mt][nt][2] + bx, acc[mt][nt][3] + by);
                *(__half2*)(dstbase + (size_t)r0 * HS + col)       = v0;
                *(__half2*)(dstbase + (size_t)(r0 + 8) * HS + col) = v1;
            }
        }
    } else {
#pragma unroll
        for (int mt = 0; mt < 4; mt++) {
#pragma unroll
            for (int nt = 0; nt < 4; nt++) {
                int col = bcol + wn + nt * 8 + 2 * t;
                float bx = __ldg(&bias[col]), by = __ldg(&bias[col + 1]);
                int r0 = brow + wm + mt * 16 + g;
                float2 v0 = make_float2(acc[mt][nt][0] + bx, acc[mt][nt][1] + by);
                float2 v1 = make_float2(acc[mt][nt][2] + bx, acc[mt][nt][3] + by);
                *(float2*)(C + (size_t)r0 * N + col)       = v0;
                *(float2*)(C + (size_t)(r0 + 8) * N + col) = v1;
            }
        }
    }
}

// =====================================================================
// fp16 flash attention: P-in-registers + cp.async double-buffered K/V.
// Per CTA: 1 head x 128 q-rows, 8 warps x 16 rows, K/V tiles of 64.
// smem (halfs): Qs[128][136], Kb[2][64][136], Vb[2][64][136]
// =====================================================================
#define QS2 136
#define KV_STG (64 * QS2)

__global__ void __launch_bounds__(256) attn_kernel()
{
    extern __shared__ __half smha[];
    __half* Qs = smha;                         // 128*136
    __half* KV = Qs + 128 * QS2;               // [buf][K|V]: Kb0,Vb0,Kb1,Vb1

    int tid  = threadIdx.x;
    int lane = tid & 31, wid = tid >> 5;
    int g = lane >> 2, t = lane & 3;
    int lm = lane & 7;
    int lq = (lane >> 3) & 1;
    int lh = lane >> 4;

    int qtile = (gridDim.x - 1) - blockIdx.x;  // heavy CTAs first
    int head  = blockIdx.y;
    const __half* Qp = g_q + (size_t)head * S_LEN * HS;
    const __half* Kp = g_k + (size_t)head * S_LEN * HS;
    const __half* Vp = g_v + (size_t)head * S_LEN * HS;

    int q0 = qtile * 128;

    // stage Q
#pragma unroll
    for (int it = 0; it < 8; it++) {
        int idx = tid + it * 256;
        int r  = idx >> 4;
        int c8 = (idx & 15) << 3;
        *(uint4*)&Qs[r * QS2 + c8] = *(const uint4*)(Qp + (size_t)(q0 + r) * HS + c8);
    }

    const float scale = 0.08838834764831845f;  // 1/sqrt(128)
    int lr   = wid * 16 + g;
    int row0 = q0 + lr;

    uint32_t smbase = (uint32_t)__cvta_generic_to_shared(smha);
    uint32_t qs_base = smbase
                     + (uint32_t)((wid * 16 + lm + lq * 8) * QS2 + lh * 8) * 2u;
    uint32_t kv0 = smbase + (uint32_t)(128 * QS2) * 2u;
    uint32_t ks_lane = (uint32_t)((lm + lh * 8) * QS2 + lq * 8) * 2u;
    uint32_t vs_lane = (uint32_t)((lm + lq * 8) * QS2 + lh * 8) * 2u;

    // cp.async staging coords: 64 rows x 128 halfs per matrix
    int p_r  = tid >> 4;              // 0..15 (x4 blocks of 16 rows)
    int p_c8 = (tid & 15) << 3;

    auto prefetch_kv = [&](int jt_, int buf) {
        uint32_t kb = kv0 + (uint32_t)(buf * 2 * KV_STG) * 2u;
        uint32_t vb = kb + (uint32_t)KV_STG * 2u;
        int k0_ = jt_ * 64;
#pragma unroll
        for (int it = 0; it < 4; it++) {
            int row = p_r + it * 16;
            uint32_t so = (uint32_t)(row * QS2 + p_c8) * 2u;
            cp_async16(kb + so, Kp + (size_t)(k0_ + row) * HS + p_c8);
            cp_async16(vb + so, Vp + (size_t)(k0_ + row) * HS + p_c8);
        }
    };

    float m0 = -FLT_MAX, m1 = -FLT_MAX, l0 = 0.f, l1 = 0.f;
    float o[16][4];
#pragma unroll
    for (int nt = 0; nt < 16; nt++)
#pragma unroll
        for (int r = 0; r < 4; r++) o[nt][r] = 0.f;

    int jmax = 2 * qtile + 1;
    prefetch_kv(0, 0);
    asm volatile("cp.async.commit_group;" ::: "memory");

    for (int jt = 0; jt <= jmax; jt++) {
        int k0 = jt * 64;
        int buf = jt & 1;
        __syncthreads();                       // done reading buf[(jt+1)&1] (iter jt-1)
        if (jt < jmax) prefetch_kv(jt + 1, buf ^ 1);
        asm volatile("cp.async.commit_group;" ::: "memory");
        asm volatile("cp.async.wait_group 1;" ::: "memory");   // group jt landed
        __syncthreads();                       // visibility

        uint32_t ks_base = kv0 + (uint32_t)(buf * 2 * KV_STG) * 2u + ks_lane;
        uint32_t vs_base = kv0 + (uint32_t)(buf * 2 * KV_STG + KV_STG) * 2u + vs_lane;

        // ---- S = Q @ K^T ----
        float sacc[8][4];
#pragma unroll
        for (int nt = 0; nt < 8; nt++)
#pragma unroll
            for (int r = 0; r < 4; r++) sacc[nt][r] = 0.f;

#pragma unroll
        for (int kk = 0; kk < 8; kk++) {
            uint32_t af[4];
            ldsm_x4(af, qs_base + (uint32_t)(kk * 16) * 2u);
#pragma unroll
            for (int np = 0; np < 4; np++) {
                uint32_t br[4];
                ldsm_x4(br, ks_base + (uint32_t)(np * 16 * QS2 + kk * 16) * 2u);
                mma_f16(sacc[2 * np],     af, &br[0], sacc[2 * np]);
                mma_f16(sacc[2 * np + 1], af, &br[2], sacc[2 * np + 1]);
            }
        }

        // ---- scale + causal mask + row max ----
        bool diag = (jt >= 2 * qtile);
        float mx0 = -FLT_MAX, mx1 = -FLT_MAX;
#pragma unroll
        for (int nt = 0; nt < 8; nt++) {
            int colb = k0 + nt * 8 + 2 * t;
            float v0 = sacc[nt][0] * scale;
            float v1 = sacc[nt][1] * scale;
            float v2 = sacc[nt][2] * scale;
            float v3 = sacc[nt][3] * scale;
            if (diag) {
                if (colb     > row0)     v0 = -FLT_MAX;
                if (colb + 1 > row0)     v1 = -FLT_MAX;
                if (colb     > row0 + 8) v2 = -FLT_MAX;
                if (colb + 1 > row0 + 8) v3 = -FLT_MAX;
            }
            sacc[nt][0] = v0; sacc[nt][1] = v1;
            sacc[nt][2] = v2; sacc[nt][3] = v3;
            mx0 = fmaxf(mx0, fmaxf(v0, v1));
            mx1 = fmaxf(mx1, fmaxf(v2, v3));
        }
        mx0 = fmaxf(mx0, __shfl_xor_sync(0xffffffffu, mx0, 1));
        mx0 = fmaxf(mx0, __shfl_xor_sync(0xffffffffu, mx0, 2));
        mx1 = fmaxf(mx1, __shfl_xor_sync(0xffffffffu, mx1, 1));
        mx1 = fmaxf(mx1, __shfl_xor_sync(0xffffffffu, mx1, 2));
        float m0n = fmaxf(m0, mx0), m1n = fmaxf(m1, mx1);

        // ---- exp + pack P directly into mma A fragments (no smem) ----
        uint32_t paf[4][4];
        float s0 = 0.f, s1 = 0.f;
#pragma unroll
        for (int kk = 0; kk < 4; kk++) {
#pragma unroll
            for (int h = 0; h < 2; h++) {
                int nt = 2 * kk + h;
                float p0 = __expf(sacc[nt][0] - m0n);
                float p1 = __expf(sacc[nt][1] - m0n);
                float p2 = __expf(sacc[nt][2] - m1n);
                float p3 = __expf(sacc[nt][3] - m1n);
                s0 += p0 + p1;
                s1 += p2 + p3;
                __half2 lo = __floats2half2_rn(p0, p1);   // rows g,   k-lo/hi pair
                __half2 hi = __floats2half2_rn(p2, p3);   // rows g+8
                paf[kk][2 * h]     = *(uint32_t*)&lo;     // a0 / a2
                paf[kk][2 * h + 1] = *(uint32_t*)&hi;     // a1 / a3
            }
        }
        s0 += __shfl_xor_sync(0xffffffffu, s0, 1);
        s0 += __shfl_xor_sync(0xffffffffu, s0, 2);
        s1 += __shfl_xor_sync(0xffffffffu, s1, 1);
        s1 += __shfl_xor_sync(0xffffffffu, s1, 2);

        float sc0 = __expf(m0 - m0n), sc1 = __expf(m1 - m1n);
        l0 = l0 * sc0 + s0;  l1 = l1 * sc1 + s1;
        m0 = m0n;            m1 = m1n;
#pragma unroll
        for (int nt = 0; nt < 16; nt++) {
            o[nt][0] *= sc0; o[nt][1] *= sc0;
            o[nt][2] *= sc1; o[nt][3] *= sc1;
        }

        // ---- O += P @ V (V via ldmatrix.trans) ----
#pragma unroll
        for (int kk = 0; kk < 4; kk++) {
#pragma unroll
            for (int np = 0; np < 8; np++) {
                uint32_t br[4];
                ldsm_x4t(br, vs_base + (uint32_t)(kk * 16 * QS2 + np * 16) * 2u);
                mma_f16(o[2 * np],     paf[kk], &br[0], o[2 * np]);
                mma_f16(o[2 * np + 1], paf[kk], &br[2], o[2 * np + 1]);
            }
        }
    }

    // ---- epilogue: normalize, store to g_ctx (fp16) ----
    float inv0 = 1.f / l0, inv1 = 1.f / l1;
    __half* dst0 = g_ctx + (size_t)row0 * HID + head * HS;
    __half* dst1 = dst0 + (size_t)8 * HID;
#pragma unroll
    for (int nt = 0; nt < 16; nt++) {
        int c = nt * 8 + 2 * t;
        *(__half2*)(dst0 + c) = __floats2half2_rn(o[nt][0] * inv0, o[nt][1] * inv0);
        *(__half2*)(dst1 + c) = __floats2half2_rn(o[nt][2] * inv1, o[nt][3] * inv1);
    }
}

// =====================================================================
// launch
// =====================================================================
extern "C" void kernel_launch(void* const* d_in, const int* in_sizes, int n_in,
                              void* d_out, int out_size)
{
    const float* hidden  = (const float*)d_in[0];
    // d_in[1] = ltor_mask (always causal tril; handled analytically)
    const float* W_qkv   = (const float*)d_in[2];
    const float* b_qkv   = (const float*)d_in[3];
    const float* W_dense = (const float*)d_in[4];
    const float* b_dense = (const float*)d_in[5];
    float* out = (float*)d_out;

    const int ATTN_SMEM = (128 * QS2 + 4 * KV_STG) * (int)sizeof(__half);  // 104448 B
    cudaFuncSetAttribute(attn_kernel,
                         cudaFuncAttributeMaxDynamicSharedMemorySize, ATTN_SMEM);
    cudaFuncSetAttribute(tc_gemm<0>,
                         cudaFuncAttributeMaxDynamicSharedMemorySize, GEMM_SMEM);
    cudaFuncSetAttribute(tc_gemm<1>,
                         cudaFuncAttributeMaxDynamicSharedMemorySize, GEMM_SMEM);

    // prep: single fused fp32 -> fp16 convert
    cvt_all_kernel<<<(N_H8 + N_WQ8 + N_WD8) / 256, 256>>>(hidden, W_qkv, W_dense);

    // 1) QKV projection
    tc_gemm<0><<<dim3(3 * HID / 128, S_LEN / 128), 256, GEMM_SMEM>>>(b_qkv, nullptr,
                                                                     HID, 3 * HID);
    // 2) causal flash attention -> g_ctx
    attn_kernel<<<dim3(16, 16), 256, ATTN_SMEM>>>();

    // 3) dense projection
    tc_gemm<1><<<dim3(HID / 128, S_LEN / 128), 256, GEMM_SMEM>>>(b_dense, out,
                                                                 HID, HID);
}